// round 13
// baseline (speedup 1.0000x reference)
#include <cuda_runtime.h>
#include <cuda_fp16.h>
#include <cstdint>

#define NN   50000
#define NE   800000
#define FIN  96
#define FH   64
#define FOUT 40
#define N2   80
#define SCAN_B 1024
#define NBLK_SCAN ((NN + SCAN_B - 1) / SCAN_B)   // 49

__device__ __align__(16) float  g_hpre[NN * FH];   // x@W1_0 + b1
__device__ __align__(16) __half g_y1h[NN * FH];    // x@W1_1  (fp16)
__device__ __align__(16) float  g_H[NN * FH];      // relu(h_pre + A y1)
__device__ __align__(16) __half g_y2h[NN * FOUT];  // H@W2_1  (fp16)
__device__ float g_dis[NN];
__device__ int   g_deg[NN];
__device__ int   g_off[NN];
__device__ int   g_cur[NN];
__device__ int   g_total;                          // atomic base for scan
__device__ __align__(8) int2 g_cw[NE];             // packed {col, w-bits}
__device__ int   g_is64;

__device__ __forceinline__ int edge_at(const void* ei, int which, int e) {
    if (g_is64) return (int)((const long long*)ei)[(size_t)which * NE + e];
    return ((const int*)ei)[(size_t)which * NE + e];
}

__device__ __forceinline__ float to_tf32(float x) {
    uint32_t y;
    asm("cvt.rna.tf32.f32 %0, %1;" : "=r"(y) : "f"(x));
    return __uint_as_float(y);
}

__device__ __forceinline__ void mma_tf32(float c[4], const uint32_t a[4], const uint32_t b[2]) {
    asm volatile(
        "mma.sync.aligned.m16n8k8.row.col.f32.tf32.tf32.f32 "
        "{%0,%1,%2,%3}, {%4,%5,%6,%7}, {%8,%9}, {%0,%1,%2,%3};"
        : "+f"(c[0]), "+f"(c[1]), "+f"(c[2]), "+f"(c[3])
        : "r"(a[0]), "r"(a[1]), "r"(a[2]), "r"(a[3]), "r"(b[0]), "r"(b[1]));
}

// ---------------- init + dtype detect (every call; no cross-replay state) ------------
__global__ void k_zero(const void* ei) {
    int i = blockIdx.x * blockDim.x + threadIdx.x;
    if (i < NN) { g_deg[i] = 0; g_cur[i] = 0; }
    if (i == 0) g_total = 0;
    if (blockIdx.x == 0 && threadIdx.x < 32) {
        const unsigned long long* p = (const unsigned long long*)ei;
        unsigned long long v0 = p[threadIdx.x];
        unsigned long long v1 = p[32 + threadIdx.x];
        int bad = (v0 >= (unsigned long long)NN) || (v1 >= (unsigned long long)NN);
        unsigned m = __ballot_sync(0xffffffffu, bad);
        if (threadIdx.x == 0) g_is64 = (m == 0u) ? 1 : 0;
    }
}

__global__ __launch_bounds__(256) void k_deg(const void* __restrict__ ei) {
    int e = blockIdx.x * blockDim.x + threadIdx.x;
    if (e < NE) {
        int r = edge_at(ei, 0, e);
        if ((unsigned)r < NN) atomicAdd(&g_deg[r], 1);
    }
}

// ---------------- k_scan: block scan + atomic range reservation + dis, one launch ----
// Segments are allocated in block-arrival order; CSR only needs disjoint in-range
// segments per row, which atomicAdd reservation guarantees.
__global__ __launch_bounds__(SCAN_B) void k_scan() {
    __shared__ int s[SCAN_B];
    __shared__ int sbase;
    const int t = threadIdx.x;
    int i = blockIdx.x * SCAN_B + t;
    int v = (i < NN) ? g_deg[i] : 0;
    if (i < NN) g_dis[i] = (v > 0) ? rsqrtf((float)v) : 0.f;
    s[t] = v;
    __syncthreads();
#pragma unroll
    for (int off = 1; off < SCAN_B; off <<= 1) {
        int tv = (t >= off) ? s[t - off] : 0;
        __syncthreads();
        s[t] += tv;
        __syncthreads();
    }
    int incl = s[t];
    if (t == SCAN_B - 1) sbase = atomicAdd(&g_total, incl);
    __syncthreads();
    if (i < NN) g_off[i] = incl - v + sbase;
}

// ---------------- bucket edges into packed CSR ----------------
__global__ __launch_bounds__(256) void k_bucket(const void* __restrict__ ei) {
    int e = blockIdx.x * blockDim.x + threadIdx.x;
    if (e >= NE) return;
    int r = edge_at(ei, 0, e);
    int c = edge_at(ei, 1, e);
    if ((unsigned)r >= NN || (unsigned)c >= NN) return;
    int slot = g_off[r] + atomicAdd(&g_cur[r], 1);
    float w = -g_dis[r] * g_dis[c];
    g_cw[slot] = make_int2(c, __float_as_int(w));
}

// ---------------- GEMM1 (tf32): h_pre = x@W1_0+b1 (f32), y1 = x@W1_1 (f16) -----------
__global__ __launch_bounds__(256) void k_gemm1(const float* __restrict__ x,
                                               const float* __restrict__ W0,
                                               const float* __restrict__ W1,
                                               const float* __restrict__ b1) {
    __shared__ float xs[64][36];
    __shared__ float ws[32][136];
    const int t    = threadIdx.x;
    const int lane = t & 31;
    const int w    = t >> 5;
    const int wr   = w >> 2;
    const int wc   = w & 3;
    const int r0   = blockIdx.x * 64;

    float acc[2][4][4];
#pragma unroll
    for (int mb = 0; mb < 2; mb++)
#pragma unroll
        for (int nb = 0; nb < 4; nb++)
#pragma unroll
            for (int q = 0; q < 4; q++) acc[mb][nb][q] = 0.f;

    for (int kc = 0; kc < FIN; kc += 32) {
        for (int idx = t; idx < 512; idx += 256) {
            int r  = idx >> 3;
            int c4 = idx & 7;
            int row = r0 + r;
            float4 v = make_float4(0.f, 0.f, 0.f, 0.f);
            if (row < NN) v = *(const float4*)&x[row * FIN + kc + c4 * 4];
            xs[r][c4 * 4 + 0] = to_tf32(v.x);
            xs[r][c4 * 4 + 1] = to_tf32(v.y);
            xs[r][c4 * 4 + 2] = to_tf32(v.z);
            xs[r][c4 * 4 + 3] = to_tf32(v.w);
        }
        for (int idx = t; idx < 32 * FH; idx += 256) {
            int kk = idx >> 6;
            int j  = idx & 63;
            int gk = kc + kk;
            ws[kk][j]      = to_tf32(W0[gk * FH + j]);
            ws[kk][64 + j] = to_tf32(W1[gk * FH + j]);
        }
        __syncthreads();

#pragma unroll
        for (int kk = 0; kk < 32; kk += 8) {
            uint32_t a[2][4];
            const int ar = lane >> 2;
            const int ak = kk + (lane & 3);
#pragma unroll
            for (int mb = 0; mb < 2; mb++) {
                int rr = wr * 32 + mb * 16 + ar;
                a[mb][0] = __float_as_uint(xs[rr][ak]);
                a[mb][1] = __float_as_uint(xs[rr + 8][ak]);
                a[mb][2] = __float_as_uint(xs[rr][ak + 4]);
                a[mb][3] = __float_as_uint(xs[rr + 8][ak + 4]);
            }
#pragma unroll
            for (int nb = 0; nb < 4; nb++) {
                uint32_t b[2];
                int col = wc * 32 + nb * 8 + (lane >> 2);
                b[0] = __float_as_uint(ws[ak][col]);
                b[1] = __float_as_uint(ws[ak + 4][col]);
                mma_tf32(acc[0][nb], a[0], b);
                mma_tf32(acc[1][nb], a[1], b);
            }
        }
        __syncthreads();
    }

#pragma unroll
    for (int mb = 0; mb < 2; mb++) {
#pragma unroll
        for (int nb = 0; nb < 4; nb++) {
            int row = r0 + wr * 32 + mb * 16 + (lane >> 2);
            int col = wc * 32 + nb * 8 + (lane & 3) * 2;
            if (col < FH) {
                float bx = b1[col], by = b1[col + 1];
                if (row < NN)
                    *(float2*)&g_hpre[row * FH + col] =
                        make_float2(acc[mb][nb][0] + bx, acc[mb][nb][1] + by);
                if (row + 8 < NN)
                    *(float2*)&g_hpre[(row + 8) * FH + col] =
                        make_float2(acc[mb][nb][2] + bx, acc[mb][nb][3] + by);
            } else {
                int c2 = col - FH;
                if (row < NN)
                    ((__half2*)g_y1h)[row * 32 + (c2 >> 1)] =
                        __floats2half2_rn(acc[mb][nb][0], acc[mb][nb][1]);
                if (row + 8 < NN)
                    ((__half2*)g_y1h)[(row + 8) * 32 + (c2 >> 1)] =
                        __floats2half2_rn(acc[mb][nb][2], acc[mb][nb][3]);
            }
        }
    }
}

// ---------------- SpMM1 (pull, warp/node, 8x unroll, f16 gather) ---------------------
__global__ __launch_bounds__(256) void k_spmm1() {
    const int wid  = threadIdx.x >> 5;
    const int lane = threadIdx.x & 31;
    const int r = blockIdx.x * 8 + wid;
    if (r >= NN) return;

    const int d = g_cur[r];
    const int2* __restrict__ cw = g_cw + g_off[r];
    const __half2* __restrict__ Y = (const __half2*)g_y1h;

    float2 a[8];
#pragma unroll
    for (int k = 0; k < 8; k++) a[k] = make_float2(0.f, 0.f);

    int jj = 0;
    for (; jj + 8 <= d; jj += 8) {
        int2 p[8];
#pragma unroll
        for (int k = 0; k < 8; k++) p[k] = __ldg(&cw[jj + k]);
#pragma unroll
        for (int k = 0; k < 8; k++) {
            float2 v = __half22float2(__ldg(&Y[p[k].x * 32 + lane]));
            float w = __int_as_float(p[k].y);
            a[k].x += w * v.x; a[k].y += w * v.y;
        }
    }
    for (; jj < d; jj++) {
        int2 p = __ldg(&cw[jj]);
        float2 v = __half22float2(__ldg(&Y[p.x * 32 + lane]));
        float w = __int_as_float(p.y);
        a[0].x += w * v.x; a[0].y += w * v.y;
    }
#pragma unroll
    for (int k = 4; k < 8; k++) { a[k - 4].x += a[k].x; a[k - 4].y += a[k].y; }
    float2 acc = make_float2(a[0].x + a[1].x + a[2].x + a[3].x,
                             a[0].y + a[1].y + a[2].y + a[3].y);
    float2 pre = ((const float2*)g_hpre)[r * 32 + lane];
    ((float2*)g_H)[r * 32 + lane] =
        make_float2(fmaxf(pre.x + acc.x, 0.f), fmaxf(pre.y + acc.y, 0.f));
}

// ---------------- GEMM2 (tf32): out = H@W2_0+b2 (f32) ; y2 = H@W2_1 (f16) ------------
__global__ __launch_bounds__(128) void k_gemm2(const float* __restrict__ W20,
                                               const float* __restrict__ W21,
                                               const float* __restrict__ b2,
                                               float* __restrict__ out) {
    __shared__ float hs[64][68];
    __shared__ float ws[64][88];
    const int t    = threadIdx.x;
    const int lane = t & 31;
    const int w    = t >> 5;
    const int r0   = blockIdx.x * 64;

    for (int idx = t; idx < 64 * FH; idx += 128) {
        int r = idx >> 6;
        int k = idx & 63;
        int row = r0 + r;
        hs[r][k] = (row < NN) ? to_tf32(g_H[row * FH + k]) : 0.f;
    }
    for (int idx = t; idx < FH * N2; idx += 128) {
        int k = idx / N2;
        int j = idx % N2;
        float v = (j < FOUT) ? W20[k * FOUT + j] : W21[k * FOUT + (j - FOUT)];
        ws[k][j] = to_tf32(v);
    }
    __syncthreads();

    float acc[10][4];
#pragma unroll
    for (int nb = 0; nb < 10; nb++)
#pragma unroll
        for (int q = 0; q < 4; q++) acc[nb][q] = 0.f;

#pragma unroll
    for (int kk = 0; kk < FH; kk += 8) {
        const int ar = lane >> 2;
        const int ak = kk + (lane & 3);
        uint32_t a[4];
        int rr = w * 16 + ar;
        a[0] = __float_as_uint(hs[rr][ak]);
        a[1] = __float_as_uint(hs[rr + 8][ak]);
        a[2] = __float_as_uint(hs[rr][ak + 4]);
        a[3] = __float_as_uint(hs[rr + 8][ak + 4]);
#pragma unroll
        for (int nb = 0; nb < 10; nb++) {
            uint32_t b[2];
            int col = nb * 8 + (lane >> 2);
            b[0] = __float_as_uint(ws[ak][col]);
            b[1] = __float_as_uint(ws[ak + 4][col]);
            mma_tf32(acc[nb], a, b);
        }
    }

#pragma unroll
    for (int nb = 0; nb < 10; nb++) {
        int row = r0 + w * 16 + (lane >> 2);
        int col = nb * 8 + (lane & 3) * 2;
        if (col < FOUT) {
            float bx = b2[col], by = b2[col + 1];
            if (row < NN)
                *(float2*)&out[row * FOUT + col] =
                    make_float2(acc[nb][0] + bx, acc[nb][1] + by);
            if (row + 8 < NN)
                *(float2*)&out[(row + 8) * FOUT + col] =
                    make_float2(acc[nb][2] + bx, acc[nb][3] + by);
        } else {
            int c2 = col - FOUT;
            if (row < NN)
                ((__half2*)g_y2h)[row * 20 + (c2 >> 1)] =
                    __floats2half2_rn(acc[nb][0], acc[nb][1]);
            if (row + 8 < NN)
                ((__half2*)g_y2h)[(row + 8) * 20 + (c2 >> 1)] =
                    __floats2half2_rn(acc[nb][2], acc[nb][3]);
        }
    }
}

// ---------------- SpMM2 (pull, warp/node, 8x unroll, f16 gather) ---------------------
__global__ __launch_bounds__(256) void k_spmm2(float* __restrict__ out) {
    const int wid  = threadIdx.x >> 5;
    const int lane = threadIdx.x & 31;
    const int r = blockIdx.x * 8 + wid;
    if (r >= NN) return;

    const int d = g_cur[r];
    const int2* __restrict__ cw = g_cw + g_off[r];
    const __half2* __restrict__ Y = (const __half2*)g_y2h;
    const bool act = lane < 20;

    float2 a[8];
#pragma unroll
    for (int k = 0; k < 8; k++) a[k] = make_float2(0.f, 0.f);

    int jj = 0;
    for (; jj + 8 <= d; jj += 8) {
        int2 p[8];
#pragma unroll
        for (int k = 0; k < 8; k++) p[k] = __ldg(&cw[jj + k]);
        if (act) {
#pragma unroll
            for (int k = 0; k < 8; k++) {
                float2 v = __half22float2(__ldg(&Y[p[k].x * 20 + lane]));
                float w = __int_as_float(p[k].y);
                a[k].x += w * v.x; a[k].y += w * v.y;
            }
        }
    }
    for (; jj < d; jj++) {
        int2 p = __ldg(&cw[jj]);
        if (act) {
            float2 v = __half22float2(__ldg(&Y[p.x * 20 + lane]));
            float w = __int_as_float(p.y);
            a[0].x += w * v.x; a[0].y += w * v.y;
        }
    }
    if (act) {
#pragma unroll
        for (int k = 4; k < 8; k++) { a[k - 4].x += a[k].x; a[k - 4].y += a[k].y; }
        float2 acc = make_float2(a[0].x + a[1].x + a[2].x + a[3].x,
                                 a[0].y + a[1].y + a[2].y + a[3].y);
        float2* o = &((float2*)out)[r * 20 + lane];
        float2 cur = *o;
        cur.x += acc.x; cur.y += acc.y;
        *o = cur;
    }
}

extern "C" void kernel_launch(void* const* d_in, const int* in_sizes, int n_in,
                              void* d_out, int out_size) {
    const float* x   = (const float*)d_in[0];
    const void*  ei  = d_in[1];
    const float* W10 = (const float*)d_in[2];
    const float* W11 = (const float*)d_in[3];
    const float* b1  = (const float*)d_in[4];
    const float* W20 = (const float*)d_in[5];
    const float* W21 = (const float*)d_in[6];
    const float* b2  = (const float*)d_in[7];
    float* out = (float*)d_out;

    k_zero  <<<(NN + 255) / 256, 256>>>(ei);
    k_deg   <<<(NE + 255) / 256, 256>>>(ei);
    k_scan  <<<NBLK_SCAN, SCAN_B>>>();
    k_bucket<<<(NE + 255) / 256, 256>>>(ei);
    k_gemm1 <<<(NN + 63) / 64, 256>>>(x, W10, W11, b1);
    k_spmm1 <<<(NN + 7) / 8, 256>>>();
    k_gemm2 <<<(NN + 63) / 64, 128>>>(W20, W21, b2, out);
    k_spmm2 <<<(NN + 7) / 8, 256>>>(out);
}

// round 14
// speedup vs baseline: 1.0890x; 1.0890x over previous
#include <cuda_runtime.h>
#include <cuda_fp16.h>
#include <cstdint>

#define NN   50000
#define NE   800000
#define FIN  96
#define FH   64
#define FOUT 40
#define N2   80
#define SCAN_B 1024
#define NBLK_SCAN ((NN + SCAN_B - 1) / SCAN_B)   // 49

__device__ __align__(16) float  g_hpre[NN * FH];   // x@W1_0 + b1
__device__ __align__(16) __half g_y1h[NN * FH];    // dis[c] * (x@W1_1)  (fp16)
__device__ __align__(16) float  g_H[NN * FH];      // relu(h_pre - dis[r]*A_sum)
__device__ __align__(16) __half g_y2h[NN * FOUT];  // dis[c] * (H@W2_1)  (fp16)
__device__ float g_dis[NN];
__device__ int   g_deg[NN];
__device__ int   g_off[NN];
__device__ int   g_cur[NN];
__device__ int   g_total;                          // atomic base for scan
__device__ int   g_colA[NE];                       // CSR col indices (4B/edge)
__device__ int   g_is64;

__device__ __forceinline__ int edge_at(const void* ei, int which, int e) {
    if (g_is64) return (int)((const long long*)ei)[(size_t)which * NE + e];
    return ((const int*)ei)[(size_t)which * NE + e];
}

__device__ __forceinline__ float to_tf32(float x) {
    uint32_t y;
    asm("cvt.rna.tf32.f32 %0, %1;" : "=r"(y) : "f"(x));
    return __uint_as_float(y);
}

__device__ __forceinline__ void mma_tf32(float c[4], const uint32_t a[4], const uint32_t b[2]) {
    asm volatile(
        "mma.sync.aligned.m16n8k8.row.col.f32.tf32.tf32.f32 "
        "{%0,%1,%2,%3}, {%4,%5,%6,%7}, {%8,%9}, {%0,%1,%2,%3};"
        : "+f"(c[0]), "+f"(c[1]), "+f"(c[2]), "+f"(c[3])
        : "r"(a[0]), "r"(a[1]), "r"(a[2]), "r"(a[3]), "r"(b[0]), "r"(b[1]));
}

// ---------------- init + dtype detect (every call; no cross-replay state) ------------
__global__ void k_zero(const void* ei) {
    int i = blockIdx.x * blockDim.x + threadIdx.x;
    if (i < NN) g_deg[i] = 0;
    if (i == 0) g_total = 0;
    if (blockIdx.x == 0 && threadIdx.x < 32) {
        const unsigned long long* p = (const unsigned long long*)ei;
        unsigned long long v0 = p[threadIdx.x];
        unsigned long long v1 = p[32 + threadIdx.x];
        int bad = (v0 >= (unsigned long long)NN) || (v1 >= (unsigned long long)NN);
        unsigned m = __ballot_sync(0xffffffffu, bad);
        if (threadIdx.x == 0) g_is64 = (m == 0u) ? 1 : 0;
    }
}

__global__ __launch_bounds__(256) void k_deg(const void* __restrict__ ei) {
    int e = blockIdx.x * blockDim.x + threadIdx.x;
    if (e < NE) {
        int r = edge_at(ei, 0, e);
        if ((unsigned)r < NN) atomicAdd(&g_deg[r], 1);
    }
}

// ---------------- k_scan: block scan + atomic range reservation + dis + cur-zero -----
__global__ __launch_bounds__(SCAN_B) void k_scan() {
    __shared__ int s[SCAN_B];
    __shared__ int sbase;
    const int t = threadIdx.x;
    int i = blockIdx.x * SCAN_B + t;
    int v = (i < NN) ? g_deg[i] : 0;
    if (i < NN) {
        g_dis[i] = (v > 0) ? rsqrtf((float)v) : 0.f;
        g_cur[i] = 0;
    }
    s[t] = v;
    __syncthreads();
#pragma unroll
    for (int off = 1; off < SCAN_B; off <<= 1) {
        int tv = (t >= off) ? s[t - off] : 0;
        __syncthreads();
        s[t] += tv;
        __syncthreads();
    }
    int incl = s[t];
    if (t == SCAN_B - 1) sbase = atomicAdd(&g_total, incl);
    __syncthreads();
    if (i < NN) g_off[i] = incl - v + sbase;
}

// ---------------- bucket edges into CSR (col only, 4B/edge) ----------------
__global__ __launch_bounds__(256) void k_bucket(const void* __restrict__ ei) {
    int e = blockIdx.x * blockDim.x + threadIdx.x;
    if (e >= NE) return;
    int r = edge_at(ei, 0, e);
    int c = edge_at(ei, 1, e);
    if ((unsigned)r >= NN || (unsigned)c >= NN) return;
    int slot = g_off[r] + atomicAdd(&g_cur[r], 1);
    g_colA[slot] = c;
}

// ---------------- GEMM1 (tf32): h_pre = x@W1_0+b1 (f32), y1s = dis*x@W1_1 (f16) ------
__global__ __launch_bounds__(256) void k_gemm1(const float* __restrict__ x,
                                               const float* __restrict__ W0,
                                               const float* __restrict__ W1,
                                               const float* __restrict__ b1) {
    __shared__ float xs[64][36];
    __shared__ float ws[32][136];
    const int t    = threadIdx.x;
    const int lane = t & 31;
    const int w    = t >> 5;
    const int wr   = w >> 2;
    const int wc   = w & 3;
    const int r0   = blockIdx.x * 64;

    float acc[2][4][4];
#pragma unroll
    for (int mb = 0; mb < 2; mb++)
#pragma unroll
        for (int nb = 0; nb < 4; nb++)
#pragma unroll
            for (int q = 0; q < 4; q++) acc[mb][nb][q] = 0.f;

    for (int kc = 0; kc < FIN; kc += 32) {
        for (int idx = t; idx < 512; idx += 256) {
            int r  = idx >> 3;
            int c4 = idx & 7;
            int row = r0 + r;
            float4 v = make_float4(0.f, 0.f, 0.f, 0.f);
            if (row < NN) v = *(const float4*)&x[row * FIN + kc + c4 * 4];
            xs[r][c4 * 4 + 0] = to_tf32(v.x);
            xs[r][c4 * 4 + 1] = to_tf32(v.y);
            xs[r][c4 * 4 + 2] = to_tf32(v.z);
            xs[r][c4 * 4 + 3] = to_tf32(v.w);
        }
        for (int idx = t; idx < 32 * FH; idx += 256) {
            int kk = idx >> 6;
            int j  = idx & 63;
            int gk = kc + kk;
            ws[kk][j]      = to_tf32(W0[gk * FH + j]);
            ws[kk][64 + j] = to_tf32(W1[gk * FH + j]);
        }
        __syncthreads();

#pragma unroll
        for (int kk = 0; kk < 32; kk += 8) {
            uint32_t a[2][4];
            const int ar = lane >> 2;
            const int ak = kk + (lane & 3);
#pragma unroll
            for (int mb = 0; mb < 2; mb++) {
                int rr = wr * 32 + mb * 16 + ar;
                a[mb][0] = __float_as_uint(xs[rr][ak]);
                a[mb][1] = __float_as_uint(xs[rr + 8][ak]);
                a[mb][2] = __float_as_uint(xs[rr][ak + 4]);
                a[mb][3] = __float_as_uint(xs[rr + 8][ak + 4]);
            }
#pragma unroll
            for (int nb = 0; nb < 4; nb++) {
                uint32_t b[2];
                int col = wc * 32 + nb * 8 + (lane >> 2);
                b[0] = __float_as_uint(ws[ak][col]);
                b[1] = __float_as_uint(ws[ak + 4][col]);
                mma_tf32(acc[0][nb], a[0], b);
                mma_tf32(acc[1][nb], a[1], b);
            }
        }
        __syncthreads();
    }

#pragma unroll
    for (int mb = 0; mb < 2; mb++) {
        int row0 = r0 + wr * 32 + mb * 16 + (lane >> 2);
        float d0 = (row0 < NN) ? g_dis[row0] : 0.f;
        float d1 = (row0 + 8 < NN) ? g_dis[row0 + 8] : 0.f;
#pragma unroll
        for (int nb = 0; nb < 4; nb++) {
            int col = wc * 32 + nb * 8 + (lane & 3) * 2;
            if (col < FH) {
                float bx = b1[col], by = b1[col + 1];
                if (row0 < NN)
                    *(float2*)&g_hpre[row0 * FH + col] =
                        make_float2(acc[mb][nb][0] + bx, acc[mb][nb][1] + by);
                if (row0 + 8 < NN)
                    *(float2*)&g_hpre[(row0 + 8) * FH + col] =
                        make_float2(acc[mb][nb][2] + bx, acc[mb][nb][3] + by);
            } else {
                int c2 = col - FH;
                if (row0 < NN)
                    ((__half2*)g_y1h)[row0 * 32 + (c2 >> 1)] =
                        __floats2half2_rn(d0 * acc[mb][nb][0], d0 * acc[mb][nb][1]);
                if (row0 + 8 < NN)
                    ((__half2*)g_y1h)[(row0 + 8) * 32 + (c2 >> 1)] =
                        __floats2half2_rn(d1 * acc[mb][nb][2], d1 * acc[mb][nb][3]);
            }
        }
    }
}

// ---------------- SpMM1 (pull, warp/node, col-only edges, f16 gather) ----------------
__global__ __launch_bounds__(256) void k_spmm1() {
    const int wid  = threadIdx.x >> 5;
    const int lane = threadIdx.x & 31;
    const int r = blockIdx.x * 8 + wid;
    if (r >= NN) return;

    const int d = g_cur[r];
    const int* __restrict__ cols = g_colA + g_off[r];
    const __half2* __restrict__ Y = (const __half2*)g_y1h;

    float2 a[8];
#pragma unroll
    for (int k = 0; k < 8; k++) a[k] = make_float2(0.f, 0.f);

    int jj = 0;
    for (; jj + 8 <= d; jj += 8) {
        int c[8];
#pragma unroll
        for (int k = 0; k < 8; k++) c[k] = __ldg(&cols[jj + k]);
#pragma unroll
        for (int k = 0; k < 8; k++) {
            float2 v = __half22float2(__ldg(&Y[c[k] * 32 + lane]));
            a[k].x += v.x; a[k].y += v.y;
        }
    }
    for (; jj < d; jj++) {
        int c = __ldg(&cols[jj]);
        float2 v = __half22float2(__ldg(&Y[c * 32 + lane]));
        a[0].x += v.x; a[0].y += v.y;
    }
#pragma unroll
    for (int k = 4; k < 8; k++) { a[k - 4].x += a[k].x; a[k - 4].y += a[k].y; }
    float2 acc = make_float2(a[0].x + a[1].x + a[2].x + a[3].x,
                             a[0].y + a[1].y + a[2].y + a[3].y);
    float ndr = -g_dis[r];
    float2 pre = ((const float2*)g_hpre)[r * 32 + lane];
    ((float2*)g_H)[r * 32 + lane] =
        make_float2(fmaxf(fmaf(ndr, acc.x, pre.x), 0.f),
                    fmaxf(fmaf(ndr, acc.y, pre.y), 0.f));
}

// ---------------- GEMM2 (tf32): out = H@W2_0+b2 (f32) ; y2s = dis*H@W2_1 (f16) -------
__global__ __launch_bounds__(128) void k_gemm2(const float* __restrict__ W20,
                                               const float* __restrict__ W21,
                                               const float* __restrict__ b2,
                                               float* __restrict__ out) {
    __shared__ float hs[64][68];
    __shared__ float ws[64][88];
    const int t    = threadIdx.x;
    const int lane = t & 31;
    const int w    = t >> 5;
    const int r0   = blockIdx.x * 64;

    for (int idx = t; idx < 64 * FH; idx += 128) {
        int r = idx >> 6;
        int k = idx & 63;
        int row = r0 + r;
        hs[r][k] = (row < NN) ? to_tf32(g_H[row * FH + k]) : 0.f;
    }
    for (int idx = t; idx < FH * N2; idx += 128) {
        int k = idx / N2;
        int j = idx % N2;
        float v = (j < FOUT) ? W20[k * FOUT + j] : W21[k * FOUT + (j - FOUT)];
        ws[k][j] = to_tf32(v);
    }
    __syncthreads();

    float acc[10][4];
#pragma unroll
    for (int nb = 0; nb < 10; nb++)
#pragma unroll
        for (int q = 0; q < 4; q++) acc[nb][q] = 0.f;

#pragma unroll
    for (int kk = 0; kk < FH; kk += 8) {
        const int ar = lane >> 2;
        const int ak = kk + (lane & 3);
        uint32_t a[4];
        int rr = w * 16 + ar;
        a[0] = __float_as_uint(hs[rr][ak]);
        a[1] = __float_as_uint(hs[rr + 8][ak]);
        a[2] = __float_as_uint(hs[rr][ak + 4]);
        a[3] = __float_as_uint(hs[rr + 8][ak + 4]);
#pragma unroll
        for (int nb = 0; nb < 10; nb++) {
            uint32_t b[2];
            int col = nb * 8 + (lane >> 2);
            b[0] = __float_as_uint(ws[ak][col]);
            b[1] = __float_as_uint(ws[ak + 4][col]);
            mma_tf32(acc[nb], a, b);
        }
    }

    {
        int row0 = r0 + w * 16 + (lane >> 2);
        float d0 = (row0 < NN) ? g_dis[row0] : 0.f;
        float d1 = (row0 + 8 < NN) ? g_dis[row0 + 8] : 0.f;
#pragma unroll
        for (int nb = 0; nb < 10; nb++) {
            int col = nb * 8 + (lane & 3) * 2;
            if (col < FOUT) {
                float bx = b2[col], by = b2[col + 1];
                if (row0 < NN)
                    *(float2*)&out[row0 * FOUT + col] =
                        make_float2(acc[nb][0] + bx, acc[nb][1] + by);
                if (row0 + 8 < NN)
                    *(float2*)&out[(row0 + 8) * FOUT + col] =
                        make_float2(acc[nb][2] + bx, acc[nb][3] + by);
            } else {
                int c2 = col - FOUT;
                if (row0 < NN)
                    ((__half2*)g_y2h)[row0 * 20 + (c2 >> 1)] =
                        __floats2half2_rn(d0 * acc[nb][0], d0 * acc[nb][1]);
                if (row0 + 8 < NN)
                    ((__half2*)g_y2h)[(row0 + 8) * 20 + (c2 >> 1)] =
                        __floats2half2_rn(d1 * acc[nb][2], d1 * acc[nb][3]);
            }
        }
    }
}

// ---------------- SpMM2 (pull, warp/node, col-only edges, f16 gather) ----------------
__global__ __launch_bounds__(256) void k_spmm2(float* __restrict__ out) {
    const int wid  = threadIdx.x >> 5;
    const int lane = threadIdx.x & 31;
    const int r = blockIdx.x * 8 + wid;
    if (r >= NN) return;

    const int d = g_cur[r];
    const int* __restrict__ cols = g_colA + g_off[r];
    const __half2* __restrict__ Y = (const __half2*)g_y2h;
    const bool act = lane < 20;

    float2 a[8];
#pragma unroll
    for (int k = 0; k < 8; k++) a[k] = make_float2(0.f, 0.f);

    int jj = 0;
    for (; jj + 8 <= d; jj += 8) {
        int c[8];
#pragma unroll
        for (int k = 0; k < 8; k++) c[k] = __ldg(&cols[jj + k]);
        if (act) {
#pragma unroll
            for (int k = 0; k < 8; k++) {
                float2 v = __half22float2(__ldg(&Y[c[k] * 20 + lane]));
                a[k].x += v.x; a[k].y += v.y;
            }
        }
    }
    for (; jj < d; jj++) {
        int c = __ldg(&cols[jj]);
        if (act) {
            float2 v = __half22float2(__ldg(&Y[c * 20 + lane]));
            a[0].x += v.x; a[0].y += v.y;
        }
    }
    if (act) {
#pragma unroll
        for (int k = 4; k < 8; k++) { a[k - 4].x += a[k].x; a[k - 4].y += a[k].y; }
        float2 acc = make_float2(a[0].x + a[1].x + a[2].x + a[3].x,
                                 a[0].y + a[1].y + a[2].y + a[3].y);
        float ndr = -g_dis[r];
        float2* o = &((float2*)out)[r * 20 + lane];
        float2 cur = *o;
        *o = make_float2(fmaf(ndr, acc.x, cur.x), fmaf(ndr, acc.y, cur.y));
    }
}

extern "C" void kernel_launch(void* const* d_in, const int* in_sizes, int n_in,
                              void* d_out, int out_size) {
    const float* x   = (const float*)d_in[0];
    const void*  ei  = d_in[1];
    const float* W10 = (const float*)d_in[2];
    const float* W11 = (const float*)d_in[3];
    const float* b1  = (const float*)d_in[4];
    const float* W20 = (const float*)d_in[5];
    const float* W21 = (const float*)d_in[6];
    const float* b2  = (const float*)d_in[7];
    float* out = (float*)d_out;

    k_zero  <<<(NN + 255) / 256, 256>>>(ei);
    k_deg   <<<(NE + 255) / 256, 256>>>(ei);
    k_scan  <<<NBLK_SCAN, SCAN_B>>>();
    k_bucket<<<(NE + 255) / 256, 256>>>(ei);
    k_gemm1 <<<(NN + 63) / 64, 256>>>(x, W10, W11, b1);
    k_spmm1 <<<(NN + 7) / 8, 256>>>();
    k_gemm2 <<<(NN + 63) / 64, 128>>>(W20, W21, b2, out);
    k_spmm2 <<<(NN + 7) / 8, 256>>>(out);
}

// round 15
// speedup vs baseline: 1.1091x; 1.0185x over previous
#include <cuda_runtime.h>
#include <cuda_fp16.h>
#include <cstdint>

#define NN   50000
#define NE   800000
#define FIN  96
#define FH   64
#define FOUT 40
#define N2   80
#define SCAN_B 1024
#define NBLK_SCAN ((NN + SCAN_B - 1) / SCAN_B)   // 49

__device__ __align__(16) float  g_hpre[NN * FH];   // x@W1_0 + b1
__device__ __align__(16) __half g_y1h[NN * FH];    // dis[c] * (x@W1_1)  (fp16)
__device__ __align__(16) float  g_H[NN * FH];      // relu(h_pre - dis[r]*A_sum)
__device__ __align__(16) __half g_y2h[NN * FOUT];  // dis[c] * (H@W2_1)  (fp16)
__device__ float g_dis[NN];
__device__ int   g_degT[NN + 1];   // [0..NN): degree counters; [NN]: scan total (memset to 0)
__device__ int   g_off[NN];
__device__ int   g_slot[NE];       // per-edge slot within its row (from k_deg's atomic)
__device__ int   g_colA[NE];       // CSR col indices (4B/edge)

// per-block dtype detection (512B probe, L2-broadcast across blocks; stateless)
__device__ __forceinline__ int detect_is64_block(const void* ei) {
    __shared__ int s_is64;
    if (threadIdx.x < 32) {
        const unsigned long long* p = (const unsigned long long*)ei;
        unsigned long long v0 = p[threadIdx.x];
        unsigned long long v1 = p[32 + threadIdx.x];
        int bad = (v0 >= (unsigned long long)NN) || (v1 >= (unsigned long long)NN);
        unsigned m = __ballot_sync(0xffffffffu, bad);
        if (threadIdx.x == 0) s_is64 = (m == 0u) ? 1 : 0;
    }
    __syncthreads();
    return s_is64;
}

__device__ __forceinline__ int edge_at(const void* ei, int which, int e, int is64) {
    if (is64) return (int)((const long long*)ei)[(size_t)which * NE + e];
    return ((const int*)ei)[(size_t)which * NE + e];
}

__device__ __forceinline__ float to_tf32(float x) {
    uint32_t y;
    asm("cvt.rna.tf32.f32 %0, %1;" : "=r"(y) : "f"(x));
    return __uint_as_float(y);
}

__device__ __forceinline__ void mma_tf32(float c[4], const uint32_t a[4], const uint32_t b[2]) {
    asm volatile(
        "mma.sync.aligned.m16n8k8.row.col.f32.tf32.tf32.f32 "
        "{%0,%1,%2,%3}, {%4,%5,%6,%7}, {%8,%9}, {%0,%1,%2,%3};"
        : "+f"(c[0]), "+f"(c[1]), "+f"(c[2]), "+f"(c[3])
        : "r"(a[0]), "r"(a[1]), "r"(a[2]), "r"(a[3]), "r"(b[0]), "r"(b[1]));
}

// ---------------- k_deg: degree count + per-edge slot record ----------------
__global__ __launch_bounds__(256) void k_deg(const void* __restrict__ ei) {
    const int is64 = detect_is64_block(ei);
    int e = blockIdx.x * blockDim.x + threadIdx.x;
    if (e < NE) {
        int r = edge_at(ei, 0, e, is64);
        int s = -1;
        if ((unsigned)r < NN) s = atomicAdd(&g_degT[r], 1);
        g_slot[e] = s;
    }
}

// ---------------- k_scan: block scan + atomic range reservation + dis ----------------
__global__ __launch_bounds__(SCAN_B) void k_scan() {
    __shared__ int s[SCAN_B];
    __shared__ int sbase;
    const int t = threadIdx.x;
    int i = blockIdx.x * SCAN_B + t;
    int v = (i < NN) ? g_degT[i] : 0;
    if (i < NN) g_dis[i] = (v > 0) ? rsqrtf((float)v) : 0.f;
    s[t] = v;
    __syncthreads();
#pragma unroll
    for (int off = 1; off < SCAN_B; off <<= 1) {
        int tv = (t >= off) ? s[t - off] : 0;
        __syncthreads();
        s[t] += tv;
        __syncthreads();
    }
    int incl = s[t];
    if (t == SCAN_B - 1) sbase = atomicAdd(&g_degT[NN], incl);
    __syncthreads();
    if (i < NN) g_off[i] = incl - v + sbase;
}

// ---------------- k_bucket: atomic-free scatter (slot precomputed) ----------------
__global__ __launch_bounds__(256) void k_bucket(const void* __restrict__ ei) {
    const int is64 = detect_is64_block(ei);
    int e = blockIdx.x * blockDim.x + threadIdx.x;
    if (e >= NE) return;
    int s = g_slot[e];
    if (s < 0) return;
    int r = edge_at(ei, 0, e, is64);
    int c = edge_at(ei, 1, e, is64);
    if ((unsigned)c >= NN) c = 0;
    g_colA[g_off[r] + s] = c;
}

// ---------------- GEMM1 (tf32): h_pre = x@W1_0+b1 (f32), y1s = dis*x@W1_1 (f16) ------
__global__ __launch_bounds__(256) void k_gemm1(const float* __restrict__ x,
                                               const float* __restrict__ W0,
                                               const float* __restrict__ W1,
                                               const float* __restrict__ b1) {
    __shared__ float xs[64][36];
    __shared__ float ws[32][136];
    const int t    = threadIdx.x;
    const int lane = t & 31;
    const int w    = t >> 5;
    const int wr   = w >> 2;
    const int wc   = w & 3;
    const int r0   = blockIdx.x * 64;

    float acc[2][4][4];
#pragma unroll
    for (int mb = 0; mb < 2; mb++)
#pragma unroll
        for (int nb = 0; nb < 4; nb++)
#pragma unroll
            for (int q = 0; q < 4; q++) acc[mb][nb][q] = 0.f;

    for (int kc = 0; kc < FIN; kc += 32) {
        for (int idx = t; idx < 512; idx += 256) {
            int r  = idx >> 3;
            int c4 = idx & 7;
            int row = r0 + r;
            float4 v = make_float4(0.f, 0.f, 0.f, 0.f);
            if (row < NN) v = *(const float4*)&x[row * FIN + kc + c4 * 4];
            xs[r][c4 * 4 + 0] = to_tf32(v.x);
            xs[r][c4 * 4 + 1] = to_tf32(v.y);
            xs[r][c4 * 4 + 2] = to_tf32(v.z);
            xs[r][c4 * 4 + 3] = to_tf32(v.w);
        }
        for (int idx = t; idx < 32 * FH; idx += 256) {
            int kk = idx >> 6;
            int j  = idx & 63;
            int gk = kc + kk;
            ws[kk][j]      = to_tf32(W0[gk * FH + j]);
            ws[kk][64 + j] = to_tf32(W1[gk * FH + j]);
        }
        __syncthreads();

#pragma unroll
        for (int kk = 0; kk < 32; kk += 8) {
            uint32_t a[2][4];
            const int ar = lane >> 2;
            const int ak = kk + (lane & 3);
#pragma unroll
            for (int mb = 0; mb < 2; mb++) {
                int rr = wr * 32 + mb * 16 + ar;
                a[mb][0] = __float_as_uint(xs[rr][ak]);
                a[mb][1] = __float_as_uint(xs[rr + 8][ak]);
                a[mb][2] = __float_as_uint(xs[rr][ak + 4]);
                a[mb][3] = __float_as_uint(xs[rr + 8][ak + 4]);
            }
#pragma unroll
            for (int nb = 0; nb < 4; nb++) {
                uint32_t b[2];
                int col = wc * 32 + nb * 8 + (lane >> 2);
                b[0] = __float_as_uint(ws[ak][col]);
                b[1] = __float_as_uint(ws[ak + 4][col]);
                mma_tf32(acc[0][nb], a[0], b);
                mma_tf32(acc[1][nb], a[1], b);
            }
        }
        __syncthreads();
    }

#pragma unroll
    for (int mb = 0; mb < 2; mb++) {
        int row0 = r0 + wr * 32 + mb * 16 + (lane >> 2);
        float d0 = (row0 < NN) ? g_dis[row0] : 0.f;
        float d1 = (row0 + 8 < NN) ? g_dis[row0 + 8] : 0.f;
#pragma unroll
        for (int nb = 0; nb < 4; nb++) {
            int col = wc * 32 + nb * 8 + (lane & 3) * 2;
            if (col < FH) {
                float bx = b1[col], by = b1[col + 1];
                if (row0 < NN)
                    *(float2*)&g_hpre[row0 * FH + col] =
                        make_float2(acc[mb][nb][0] + bx, acc[mb][nb][1] + by);
                if (row0 + 8 < NN)
                    *(float2*)&g_hpre[(row0 + 8) * FH + col] =
                        make_float2(acc[mb][nb][2] + bx, acc[mb][nb][3] + by);
            } else {
                int c2 = col - FH;
                if (row0 < NN)
                    ((__half2*)g_y1h)[row0 * 32 + (c2 >> 1)] =
                        __floats2half2_rn(d0 * acc[mb][nb][0], d0 * acc[mb][nb][1]);
                if (row0 + 8 < NN)
                    ((__half2*)g_y1h)[(row0 + 8) * 32 + (c2 >> 1)] =
                        __floats2half2_rn(d1 * acc[mb][nb][2], d1 * acc[mb][nb][3]);
            }
        }
    }
}

// ---------------- SpMM1 (pull, warp/node, col-only edges, f16 gather) ----------------
__global__ __launch_bounds__(256) void k_spmm1() {
    const int wid  = threadIdx.x >> 5;
    const int lane = threadIdx.x & 31;
    const int r = blockIdx.x * 8 + wid;
    if (r >= NN) return;

    const int d = g_degT[r];
    const int* __restrict__ cols = g_colA + g_off[r];
    const __half2* __restrict__ Y = (const __half2*)g_y1h;

    float2 a[8];
#pragma unroll
    for (int k = 0; k < 8; k++) a[k] = make_float2(0.f, 0.f);

    int jj = 0;
    for (; jj + 8 <= d; jj += 8) {
        int c[8];
#pragma unroll
        for (int k = 0; k < 8; k++) c[k] = __ldg(&cols[jj + k]);
#pragma unroll
        for (int k = 0; k < 8; k++) {
            float2 v = __half22float2(__ldg(&Y[c[k] * 32 + lane]));
            a[k].x += v.x; a[k].y += v.y;
        }
    }
    for (; jj < d; jj++) {
        int c = __ldg(&cols[jj]);
        float2 v = __half22float2(__ldg(&Y[c * 32 + lane]));
        a[0].x += v.x; a[0].y += v.y;
    }
#pragma unroll
    for (int k = 4; k < 8; k++) { a[k - 4].x += a[k].x; a[k - 4].y += a[k].y; }
    float2 acc = make_float2(a[0].x + a[1].x + a[2].x + a[3].x,
                             a[0].y + a[1].y + a[2].y + a[3].y);
    float ndr = -g_dis[r];
    float2 pre = ((const float2*)g_hpre)[r * 32 + lane];
    ((float2*)g_H)[r * 32 + lane] =
        make_float2(fmaxf(fmaf(ndr, acc.x, pre.x), 0.f),
                    fmaxf(fmaf(ndr, acc.y, pre.y), 0.f));
}

// ---------------- GEMM2 (tf32): out = H@W2_0+b2 (f32) ; y2s = dis*H@W2_1 (f16) -------
__global__ __launch_bounds__(128) void k_gemm2(const float* __restrict__ W20,
                                               const float* __restrict__ W21,
                                               const float* __restrict__ b2,
                                               float* __restrict__ out) {
    __shared__ float hs[64][68];
    __shared__ float ws[64][88];
    const int t    = threadIdx.x;
    const int lane = t & 31;
    const int w    = t >> 5;
    const int r0   = blockIdx.x * 64;

    for (int idx = t; idx < 64 * FH; idx += 128) {
        int r = idx >> 6;
        int k = idx & 63;
        int row = r0 + r;
        hs[r][k] = (row < NN) ? to_tf32(g_H[row * FH + k]) : 0.f;
    }
    for (int idx = t; idx < FH * N2; idx += 128) {
        int k = idx / N2;
        int j = idx % N2;
        float v = (j < FOUT) ? W20[k * FOUT + j] : W21[k * FOUT + (j - FOUT)];
        ws[k][j] = to_tf32(v);
    }
    __syncthreads();

    float acc[10][4];
#pragma unroll
    for (int nb = 0; nb < 10; nb++)
#pragma unroll
        for (int q = 0; q < 4; q++) acc[nb][q] = 0.f;

#pragma unroll
    for (int kk = 0; kk < FH; kk += 8) {
        const int ar = lane >> 2;
        const int ak = kk + (lane & 3);
        uint32_t a[4];
        int rr = w * 16 + ar;
        a[0] = __float_as_uint(hs[rr][ak]);
        a[1] = __float_as_uint(hs[rr + 8][ak]);
        a[2] = __float_as_uint(hs[rr][ak + 4]);
        a[3] = __float_as_uint(hs[rr + 8][ak + 4]);
#pragma unroll
        for (int nb = 0; nb < 10; nb++) {
            uint32_t b[2];
            int col = nb * 8 + (lane >> 2);
            b[0] = __float_as_uint(ws[ak][col]);
            b[1] = __float_as_uint(ws[ak + 4][col]);
            mma_tf32(acc[nb], a, b);
        }
    }

    {
        int row0 = r0 + w * 16 + (lane >> 2);
        float d0 = (row0 < NN) ? g_dis[row0] : 0.f;
        float d1 = (row0 + 8 < NN) ? g_dis[row0 + 8] : 0.f;
#pragma unroll
        for (int nb = 0; nb < 10; nb++) {
            int col = nb * 8 + (lane & 3) * 2;
            if (col < FOUT) {
                float bx = b2[col], by = b2[col + 1];
                if (row0 < NN)
                    *(float2*)&out[row0 * FOUT + col] =
                        make_float2(acc[nb][0] + bx, acc[nb][1] + by);
                if (row0 + 8 < NN)
                    *(float2*)&out[(row0 + 8) * FOUT + col] =
                        make_float2(acc[nb][2] + bx, acc[nb][3] + by);
            } else {
                int c2 = col - FOUT;
                if (row0 < NN)
                    ((__half2*)g_y2h)[row0 * 20 + (c2 >> 1)] =
                        __floats2half2_rn(d0 * acc[nb][0], d0 * acc[nb][1]);
                if (row0 + 8 < NN)
                    ((__half2*)g_y2h)[(row0 + 8) * 20 + (c2 >> 1)] =
                        __floats2half2_rn(d1 * acc[nb][2], d1 * acc[nb][3]);
            }
        }
    }
}

// ---------------- SpMM2 (pull, warp/node, col-only edges, f16 gather) ----------------
__global__ __launch_bounds__(256) void k_spmm2(float* __restrict__ out) {
    const int wid  = threadIdx.x >> 5;
    const int lane = threadIdx.x & 31;
    const int r = blockIdx.x * 8 + wid;
    if (r >= NN) return;

    const int d = g_degT[r];
    const int* __restrict__ cols = g_colA + g_off[r];
    const __half2* __restrict__ Y = (const __half2*)g_y2h;
    const bool act = lane < 20;

    float2 a[8];
#pragma unroll
    for (int k = 0; k < 8; k++) a[k] = make_float2(0.f, 0.f);

    int jj = 0;
    for (; jj + 8 <= d; jj += 8) {
        int c[8];
#pragma unroll
        for (int k = 0; k < 8; k++) c[k] = __ldg(&cols[jj + k]);
        if (act) {
#pragma unroll
            for (int k = 0; k < 8; k++) {
                float2 v = __half22float2(__ldg(&Y[c[k] * 20 + lane]));
                a[k].x += v.x; a[k].y += v.y;
            }
        }
    }
    for (; jj < d; jj++) {
        int c = __ldg(&cols[jj]);
        if (act) {
            float2 v = __half22float2(__ldg(&Y[c * 20 + lane]));
            a[0].x += v.x; a[0].y += v.y;
        }
    }
    if (act) {
#pragma unroll
        for (int k = 4; k < 8; k++) { a[k - 4].x += a[k].x; a[k - 4].y += a[k].y; }
        float2 acc = make_float2(a[0].x + a[1].x + a[2].x + a[3].x,
                                 a[0].y + a[1].y + a[2].y + a[3].y);
        float ndr = -g_dis[r];
        float2* o = &((float2*)out)[r * 20 + lane];
        float2 cur = *o;
        *o = make_float2(fmaf(ndr, acc.x, cur.x), fmaf(ndr, acc.y, cur.y));
    }
}

extern "C" void kernel_launch(void* const* d_in, const int* in_sizes, int n_in,
                              void* d_out, int out_size) {
    const float* x   = (const float*)d_in[0];
    const void*  ei  = d_in[1];
    const float* W10 = (const float*)d_in[2];
    const float* W11 = (const float*)d_in[3];
    const float* b1  = (const float*)d_in[4];
    const float* W20 = (const float*)d_in[5];
    const float* W21 = (const float*)d_in[6];
    const float* b2  = (const float*)d_in[7];
    float* out = (float*)d_out;

    void* degT_ptr = nullptr;
    cudaGetSymbolAddress(&degT_ptr, g_degT);
    cudaMemsetAsync(degT_ptr, 0, (NN + 1) * sizeof(int));

    k_deg   <<<(NE + 255) / 256, 256>>>(ei);
    k_scan  <<<NBLK_SCAN, SCAN_B>>>();
    k_bucket<<<(NE + 255) / 256, 256>>>(ei);
    k_gemm1 <<<(NN + 63) / 64, 256>>>(x, W10, W11, b1);
    k_spmm1 <<<(NN + 7) / 8, 256>>>();
    k_gemm2 <<<(NN + 63) / 64, 128>>>(W20, W21, b2, out);
    k_spmm2 <<<(NN + 7) / 8, 256>>>(out);
}